// round 15
// baseline (speedup 1.0000x reference)
#include <cuda_runtime.h>
#include <cuda_bf16.h>
#include <cuda_fp16.h>
#include <cstdint>

#define NODES   50000
#define MAXE    800000
#define INDIM   128
#define HH      256     // HEADS*HIDDEN
#define HEADS   4
#define HID     64
#define EPSV    1e-5f
#define NEG     0.2f

// ---------------- PTX helpers (base sm_103-safe) ----------------
__device__ __forceinline__ uint32_t smem_to_u32(const void* p) {
    uint32_t a;
    asm("{ .reg .u64 t; cvta.to.shared.u64 t, %1; cvt.u32.u64 %0, t; }" : "=r"(a) : "l"(p));
    return a;
}
#define LDSM_X4(r0, r1, r2, r3, addr) \
    asm volatile("ldmatrix.sync.aligned.m8n8.x4.shared.b16 {%0,%1,%2,%3}, [%4];" \
        : "=r"(r0), "=r"(r1), "=r"(r2), "=r"(r3) : "r"(addr))
#define MMA_BF16(d, a, b) \
    asm volatile("mma.sync.aligned.m16n8k16.row.col.f32.bf16.bf16.f32 " \
        "{%0,%1,%2,%3}, {%4,%5,%6,%7}, {%8,%9}, {%0,%1,%2,%3};" \
        : "+f"((d)[0]), "+f"((d)[1]), "+f"((d)[2]), "+f"((d)[3]) \
        : "r"((a)[0]), "r"((a)[1]), "r"((a)[2]), "r"((a)[3]), "r"((b)[0]), "r"((b)[1]))

// -------- device scratch (no allocation allowed) --------
__device__ uint32_t g_hlh[NODES * 128];     // hl as packed half2 (cols 2i, 2i+1)
__device__ float g_agg[NODES * HH];
__device__ float g_asrc[NODES * HEADS];
__device__ float g_adst[NODES * HEADS];
__device__ float g_sums[1024];              // [0:256) s1 [256:512) sq1 [512:768) s2 [768:1024) sq2
__device__ float g_scale[256];
__device__ float g_mean[256];
__device__ float g_rowbias[256];
__device__ uint16_t g_Wt_hi[256 * 256];     // W^T split bf16 hi [n][k]
__device__ uint16_t g_Wt_lo[256 * 256];     // bf16 lo residual  [n][k]
__device__ uint16_t g_xh[NODES * INDIM];    // x split hi
__device__ uint16_t g_xl[NODES * INDIM];    // x split lo
__device__ uint16_t g_h2h[NODES * HH];      // post-BN2+ReLU split hi
__device__ uint16_t g_h2l[NODES * HH];      // split lo
// CSR build scratch
__device__ int g_deg[NODES];
__device__ int g_rowptr[NODES];
__device__ int g_cursor[NODES];
__device__ int g_bsums[256];
__device__ int g_csr[MAXE + NODES];

// ---------------- init: deg=1, clear all BN sums ----------------
__global__ void k_init(int n) {
    int i = blockIdx.x * blockDim.x + threadIdx.x;
    if (i < n) g_deg[i] = 1;
    if (i < 1024) g_sums[i] = 0.f;
}

// column stats into caller-chosen slots
__global__ void k_colstats(const float* __restrict__ x, int n, int C,
                           float* __restrict__ sums, float* __restrict__ sumsq) {
    int c = threadIdx.x;
    float s = 0.f, s2 = 0.f;
    for (int r = blockIdx.x; r < n; r += gridDim.x) {
        float v = x[(size_t)r * C + c];
        s += v; s2 += v * v;
    }
    atomicAdd(&sums[c], s);
    atomicAdd(&sumsq[c], s2);
}

// BN2 finalize: mean + scale (no fold)
__global__ void k_bnfinal(const float* __restrict__ gamma,
                          const float* __restrict__ sums, const float* __restrict__ sumsq,
                          int C, int n) {
    int c = threadIdx.x;
    if (c >= C) return;
    float mean = sums[c] / (float)n;
    float var  = sumsq[c] / (float)n - mean * mean;
    g_scale[c] = rsqrtf(var + EPSV) * gamma[c];
    g_mean[c]  = mean;
}

// BN1 fold: per-block recompute scale/shift from raw sums, then rowbias dot.
// grid = 256 blocks (one per output col j), 128 threads (K=INDIM).
__global__ void k_bn1fold(const float* __restrict__ gamma, const float* __restrict__ beta,
                          const float* __restrict__ W, int n) {
    __shared__ float ssh[128];
    __shared__ float red[128];
    int j = blockIdx.x, t = threadIdx.x;
    float mean = g_sums[t] / (float)n;
    float var  = g_sums[256 + t] / (float)n - mean * mean;
    float sc   = rsqrtf(var + EPSV) * gamma[t];
    float sh   = beta[t] - mean * sc;
    ssh[t] = sh;
    if (j == 0) g_scale[t] = sc;          // consumed by k_prep1 (launched after)
    __syncthreads();
    red[t] = ssh[t] * W[(size_t)t * HH + j];
    __syncthreads();
    for (int off = 64; off; off >>= 1) { if (t < off) red[t] += red[t + off]; __syncthreads(); }
    if (t == 0) g_rowbias[j] = red[0];
}

// ---------------- split helpers ----------------
__device__ __forceinline__ void splitf(float x, uint16_t& h, uint16_t& l) {
    __nv_bfloat16 bh = __float2bfloat16(x);
    float r = x - __bfloat162float(bh);
    __nv_bfloat16 bl = __float2bfloat16(r);
    h = __bfloat16_as_ushort(bh);
    l = __bfloat16_as_ushort(bl);
}

// merged: W1 transpose+split (with BN colscale) AND x split, partitioned by blockIdx
// blocks [0, 128): prepw (256*128 elems); blocks [128, ...): prepx (n*128 elems)
__global__ void k_prep1(const float* __restrict__ x, const float* __restrict__ W, int n) {
    int b = blockIdx.x, t = threadIdx.x;
    if (b < 128) {
        int idx = b * 256 + t;                 // idx = nn*K + k, K=INDIM
        int nn = idx >> 7, k = idx & 127;
        float v = W[(size_t)k * 256 + nn] * g_scale[k];
        uint16_t h, l;
        splitf(v, h, l);
        g_Wt_hi[(size_t)nn * INDIM + k] = h;
        g_Wt_lo[(size_t)nn * INDIM + k] = l;
    } else {
        int i = (b - 128) * 256 + t;
        if (i < n * INDIM) {
            uint16_t h, l;
            splitf(x[i], h, l);
            g_xh[i] = h;
            g_xl[i] = l;
        }
    }
}

// W2 transpose+split (no colscale)
__global__ void k_prepw2(const float* __restrict__ W) {
    int idx = blockIdx.x * blockDim.x + threadIdx.x;   // idx = nn*256 + k
    int nn = idx >> 8, k = idx & 255;
    float v = W[(size_t)k * 256 + nn];
    uint16_t h, l;
    splitf(v, h, l);
    g_Wt_hi[idx] = h;
    g_Wt_lo[idx] = l;
}

// ---------------- HMMA GEMM: static smem, register-prefetch double buffer ------------
// Inputs pre-split bf16 hi/lo. Writes hl as packed half2; attn dots fused in epilogue.
#define SPITCH 40

__global__ __launch_bounds__(256)
void k_mmagemm(const uint16_t* __restrict__ Ah, const uint16_t* __restrict__ Al,
               uint32_t* __restrict__ Chl, int M, int K,
               const float* __restrict__ rowbias,
               const float* __restrict__ atts, const float* __restrict__ attd) {
    __shared__ __align__(16) uint16_t As_hi[128 * SPITCH];
    __shared__ __align__(16) uint16_t As_lo[128 * SPITCH];
    __shared__ __align__(16) uint16_t Bs_hi[128 * SPITCH];
    __shared__ __align__(16) uint16_t Bs_lo[128 * SPITCH];

    const int tid = threadIdx.x, lane = tid & 31, wid = tid >> 5;
    const int warpM = wid >> 1, warpN = wid & 1;
    const int rowBase = blockIdx.y * 128;
    const int colBase = blockIdx.x * 128;

    const uint32_t sAh = smem_to_u32(As_hi), sAl = smem_to_u32(As_lo);
    const uint32_t sBh = smem_to_u32(Bs_hi), sBl = smem_to_u32(Bs_lo);

    const int nch = K >> 5;
    float acc[2][8][4] = {};
    uint2 fAh[4], fAl[4], fBh[4], fBl[4];   // next-chunk prefetch registers

    auto gload = [&](int k0) {
#pragma unroll
        for (int it = 0; it < 4; it++) {
            int i = tid + it * 256;
            int r = i >> 3, q = i & 7;
            int gr = rowBase + r;
            uint2 vh = make_uint2(0u, 0u), vl = make_uint2(0u, 0u);
            if (gr < M) {
                size_t o = (size_t)gr * K + k0 + q * 4;
                vh = *(const uint2*)(Ah + o);
                vl = *(const uint2*)(Al + o);
            }
            fAh[it] = vh; fAl[it] = vl;
            size_t ob = (size_t)(colBase + r) * K + k0 + q * 4;
            fBh[it] = *(const uint2*)(g_Wt_hi + ob);
            fBl[it] = *(const uint2*)(g_Wt_lo + ob);
        }
    };

    gload(0);

    for (int ch = 0; ch < nch; ch++) {
        // commit prefetched chunk to smem
#pragma unroll
        for (int it = 0; it < 4; it++) {
            int i = tid + it * 256;
            int r = i >> 3, q = i & 7;
            int off = r * SPITCH + q * 4;
            *(uint2*)(As_hi + off) = fAh[it];
            *(uint2*)(As_lo + off) = fAl[it];
            *(uint2*)(Bs_hi + off) = fBh[it];
            *(uint2*)(Bs_lo + off) = fBl[it];
        }
        __syncthreads();
        if (ch + 1 < nch) gload((ch + 1) << 5);   // overlaps with MMAs below

#pragma unroll
        for (int s = 0; s < 2; s++) {
            uint32_t ah[2][4], al[2][4];
#pragma unroll
            for (int mt = 0; mt < 2; mt++) {
                int rA = warpM * 32 + mt * 16 + (lane & 15);
                int kA = s * 16 + ((lane & 16) ? 8 : 0);
                uint32_t byteOff = (uint32_t)(rA * SPITCH + kA) * 2;
                LDSM_X4(ah[mt][0], ah[mt][1], ah[mt][2], ah[mt][3], sAh + byteOff);
                LDSM_X4(al[mt][0], al[mt][1], al[mt][2], al[mt][3], sAl + byteOff);
            }
            uint32_t bh[8][2], bl[8][2];
#pragma unroll
            for (int p = 0; p < 4; p++) {
                int g = lane >> 3;
                int nB = warpN * 64 + p * 16 + ((g & 2) ? 8 : 0) + (lane & 7);
                int kB = s * 16 + ((g & 1) ? 8 : 0);
                uint32_t byteOff = (uint32_t)(nB * SPITCH + kB) * 2;
                LDSM_X4(bh[2*p][0], bh[2*p][1], bh[2*p+1][0], bh[2*p+1][1], sBh + byteOff);
                LDSM_X4(bl[2*p][0], bl[2*p][1], bl[2*p+1][0], bl[2*p+1][1], sBl + byteOff);
            }
#pragma unroll
            for (int mt = 0; mt < 2; mt++)
#pragma unroll
                for (int nt = 0; nt < 8; nt++) {
                    MMA_BF16(acc[mt][nt], ah[mt], bh[nt]);
                    MMA_BF16(acc[mt][nt], ah[mt], bl[nt]);
                    MMA_BF16(acc[mt][nt], al[mt], bh[nt]);
                }
        }
        __syncthreads();
    }

    // ---- epilogue: rowbias, half2 store, fused attention dots ----
    if (rowbias) {
#pragma unroll
        for (int nt = 0; nt < 8; nt++) {
            int col = colBase + warpN * 64 + nt * 8 + (lane & 3) * 2;
            float b0 = rowbias[col], b1 = rowbias[col + 1];
#pragma unroll
            for (int mt = 0; mt < 2; mt++) {
                acc[mt][nt][0] += b0; acc[mt][nt][1] += b1;
                acc[mt][nt][2] += b0; acc[mt][nt][3] += b1;
            }
        }
    }
#pragma unroll
    for (int mt = 0; mt < 2; mt++) {
        int r0 = rowBase + warpM * 32 + mt * 16 + (lane >> 2);
#pragma unroll
        for (int half = 0; half < 2; half++) {
            int row = r0 + half * 8;
            if (row >= M) continue;
#pragma unroll
            for (int nt = 0; nt < 8; nt++) {
                int col = colBase + warpN * 64 + nt * 8 + (lane & 3) * 2;  // even
                __half2 hv = __floats2half2_rn(acc[mt][nt][half * 2], acc[mt][nt][half * 2 + 1]);
                Chl[(size_t)row * 128 + (col >> 1)] = *(uint32_t*)&hv;
            }
        }
    }
    // attention dots from fp32 accumulators (head h = this warp's 64-col span)
    {
        int h = (colBase >> 6) + warpN;
        const float* As_v = atts + h * 64;
        const float* Ad_v = attd + h * 64;
#pragma unroll
        for (int mt = 0; mt < 2; mt++) {
#pragma unroll
            for (int half = 0; half < 2; half++) {
                float ds = 0.f, dd = 0.f;
#pragma unroll
                for (int nt = 0; nt < 8; nt++) {
                    int cw = nt * 8 + (lane & 3) * 2;
                    float v0 = acc[mt][nt][half * 2], v1 = acc[mt][nt][half * 2 + 1];
                    ds += v0 * As_v[cw] + v1 * As_v[cw + 1];
                    dd += v0 * Ad_v[cw] + v1 * Ad_v[cw + 1];
                }
                ds += __shfl_xor_sync(0xffffffffu, ds, 1);
                ds += __shfl_xor_sync(0xffffffffu, ds, 2);
                dd += __shfl_xor_sync(0xffffffffu, dd, 1);
                dd += __shfl_xor_sync(0xffffffffu, dd, 2);
                int row = rowBase + warpM * 32 + mt * 16 + half * 8 + (lane >> 2);
                if ((lane & 3) == 0 && row < M) {
                    g_asrc[row * HEADS + h] = ds;
                    g_adst[row * HEADS + h] = dd;
                }
            }
        }
    }
}

// ---------------- CSR build ----------------
__global__ void k_hist(const int* __restrict__ dstp, int E) {
    int i = blockIdx.x * blockDim.x + threadIdx.x;
    if (i < E) atomicAdd(&g_deg[dstp[i]], 1);
}
__global__ void k_scan1(int n) {
    __shared__ int sh[256];
    int tid = threadIdx.x;
    int i = blockIdx.x * 256 + tid;
    int v = (i < n) ? g_deg[i] : 0;
    sh[tid] = v; __syncthreads();
    for (int off = 1; off < 256; off <<= 1) {
        int t = (tid >= off) ? sh[tid - off] : 0;
        __syncthreads();
        sh[tid] += t;
        __syncthreads();
    }
    if (i < n) g_rowptr[i] = sh[tid] - v;
    if (tid == 255) g_bsums[blockIdx.x] = sh[255];
}
__global__ void k_scan2(int nb) {
    __shared__ int sh[256];
    int tid = threadIdx.x;
    int v = (tid < nb) ? g_bsums[tid] : 0;
    sh[tid] = v; __syncthreads();
    for (int off = 1; off < 256; off <<= 1) {
        int t = (tid >= off) ? sh[tid - off] : 0;
        __syncthreads();
        sh[tid] += t;
        __syncthreads();
    }
    if (tid < nb) g_bsums[tid] = sh[tid] - v;
}
__global__ void k_scan3(int n) {
    int i = blockIdx.x * 256 + threadIdx.x;
    if (i < n) {
        int r = g_rowptr[i] + g_bsums[blockIdx.x];
        g_rowptr[i] = r;
        g_cursor[i] = r;
    }
}
__global__ void k_scatter(const int* __restrict__ srcp, const int* __restrict__ dstp,
                          int E, int n) {
    int i = blockIdx.x * blockDim.x + threadIdx.x;
    int Et = E + n;
    if (i >= Et) return;
    int s, d;
    if (i < E) { s = srcp[i]; d = dstp[i]; }
    else       { s = d = i - E; }
    int pos = atomicAdd(&g_cursor[d], 1);
    g_csr[pos] = s;
}

// ---------------- gather aggregation: warp per dst node, fp16 features ----------------
// lane owns cols {2*lane, 2*lane+1} of each head.
template <int LAYER>
__global__ void k_gather(const float* __restrict__ bias, float* __restrict__ out, int n) {
    int d = (blockIdx.x * blockDim.x + threadIdx.x) >> 5;
    int lane = threadIdx.x & 31;
    if (d >= n) return;

    float adv = 0.f;
    if (lane < HEADS) adv = g_adst[d * HEADS + lane];

    int e   = g_rowptr[d];
    int end = g_cursor[d];

    float acc[8] = {};
    float den = 0.f;
    int s = (e < end) ? g_csr[e] : 0;
#pragma unroll 2
    for (; e < end; e++) {
        int sn = (e + 1 < end) ? __ldg(g_csr + e + 1) : 0;   // prefetch next index
        float wl = 0.f;
        if (lane < HEADS) {
            float a = g_asrc[s * HEADS + lane] + adv;
            a = (a > 0.f) ? a : NEG * a;
            wl = __expf(a);
            den += wl;
        }
        const uint32_t* hr = g_hlh + (size_t)s * 128;
#pragma unroll
        for (int h = 0; h < HEADS; h++) {
            float wh = __shfl_sync(0xffffffffu, wl, h);
            uint32_t p = __ldg(hr + h * 32 + lane);
            float2 f = __half22float2(*(__half2*)&p);
            acc[2*h]   += wh * f.x;
            acc[2*h+1] += wh * f.y;
        }
        s = sn;
    }
    float dv[4];
#pragma unroll
    for (int h = 0; h < HEADS; h++) dv[h] = __shfl_sync(0xffffffffu, den, h);

    if (LAYER == 1) {
        float* orow = g_agg + (size_t)d * HH;
#pragma unroll
        for (int h = 0; h < HEADS; h++) {
            int c0 = h * 64 + 2 * lane;
            orow[c0]     = acc[2*h]   / dv[h] + bias[c0];
            orow[c0 + 1] = acc[2*h+1] / dv[h] + bias[c0 + 1];
        }
    } else {
        float v0 = 0.f, v1 = 0.f;
#pragma unroll
        for (int h = 0; h < HEADS; h++) {
            v0 += acc[2*h]   / dv[h];
            v1 += acc[2*h+1] / dv[h];
        }
        int c0 = 2 * lane;
        out[d * HID + c0]     = 0.25f * v0 + bias[c0];
        out[d * HID + c0 + 1] = 0.25f * v1 + bias[c0 + 1];
    }
}

// BN2 normalize + ReLU -> split bf16 (feeds GEMM2 directly)
__global__ void k_bnrelu(const float* __restrict__ beta, int n) {
    size_t i = (size_t)blockIdx.x * blockDim.x + threadIdx.x;
    if (i >= (size_t)n * HH) return;
    int c = (int)(i & 255);
    float v = (g_agg[i] - g_mean[c]) * g_scale[c] + beta[c];
    v = (v > 0.f) ? v : 0.f;
    uint16_t h, l;
    splitf(v, h, l);
    g_h2h[i] = h;
    g_h2l[i] = l;
}

// ---------------- host launcher ----------------
extern "C" void kernel_launch(void* const* d_in, const int* in_sizes, int n_in,
                              void* d_out, int out_size) {
    const float* x        = (const float*)d_in[0];
    const int*   ei       = (const int*)d_in[1];      // int32 (JAX x64 disabled)
    const float* gamma1   = (const float*)d_in[2];
    const float* beta1    = (const float*)d_in[3];
    const float* W1       = (const float*)d_in[4];
    const float* att_src1 = (const float*)d_in[5];
    const float* att_dst1 = (const float*)d_in[6];
    const float* bias1    = (const float*)d_in[7];
    const float* gamma2   = (const float*)d_in[8];
    const float* beta2    = (const float*)d_in[9];
    const float* W2       = (const float*)d_in[10];
    const float* att_src2 = (const float*)d_in[11];
    const float* att_dst2 = (const float*)d_in[12];
    const float* bias2    = (const float*)d_in[13];

    int n = in_sizes[0] / INDIM;
    int E = in_sizes[1] / 2;
    const int* srcp = ei;
    const int* dstp = ei + E;
    float* out = (float*)d_out;

    float *p_agg, *p_sums;
    cudaGetSymbolAddress((void**)&p_agg,  g_agg);
    cudaGetSymbolAddress((void**)&p_sums, g_sums);
    uint32_t* p_hlh;
    cudaGetSymbolAddress((void**)&p_hlh, g_hlh);
    uint16_t *p_xh, *p_xl, *p_h2h, *p_h2l;
    cudaGetSymbolAddress((void**)&p_xh,  g_xh);
    cudaGetSymbolAddress((void**)&p_xl,  g_xl);
    cudaGetSymbolAddress((void**)&p_h2h, g_h2h);
    cudaGetSymbolAddress((void**)&p_h2l, g_h2l);

    int Et = E + n;
    int featElems = n * HH;
    int scanBlocks = (n + 255) / 256;
    dim3 gemmGrid(2, (n + 127) / 128);

    // ---- init (deg=1 + clear all BN sums) + CSR build ----
    k_init<<<scanBlocks, 256>>>(n);
    k_hist<<<(E + 255) / 256, 256>>>(dstp, E);
    k_scan1<<<scanBlocks, 256>>>(n);
    k_scan2<<<1, 256>>>(scanBlocks);
    k_scan3<<<scanBlocks, 256>>>(n);
    k_scatter<<<(Et + 255) / 256, 256>>>(srcp, dstp, E, n);

    // ---- BN1 stats + fold (colscale into W1 split, rank-1 rowbias) ----
    k_colstats<<<512, INDIM>>>(x, n, INDIM, p_sums, p_sums + 256);
    k_bn1fold<<<HH, 128>>>(gamma1, beta1, W1, n);

    // ---- GAT1 ----
    k_prep1<<<128 + (n * INDIM + 255) / 256, 256>>>(x, W1, n);
    k_mmagemm<<<gemmGrid, 256>>>(p_xh, p_xl, p_hlh, n, INDIM,
                                 g_rowbias, att_src1, att_dst1);
    k_gather<1><<<(n * 32 + 255) / 256, 256>>>(bias1, nullptr, n);

    // ---- BN2 + ReLU (stats over g_agg, then normalize -> split bf16) ----
    k_colstats<<<512, HH>>>(p_agg, n, HH, p_sums + 512, p_sums + 768);
    k_bnfinal<<<1, HH>>>(gamma2, p_sums + 512, p_sums + 768, HH, n);
    k_bnrelu<<<(featElems + 255) / 256, 256>>>(beta2, n);

    // ---- GAT2 ----
    k_prepw2<<<256, 256>>>(W2);
    k_mmagemm<<<gemmGrid, 256>>>(p_h2h, p_h2l, p_hlh, n, HH,
                                 nullptr, att_src2, att_dst2);
    k_gather<2><<<(n * 32 + 255) / 256, 256>>>(bias2, out, n);
}

// round 16
// speedup vs baseline: 1.3859x; 1.3859x over previous
#include <cuda_runtime.h>
#include <cuda_bf16.h>
#include <cuda_fp16.h>
#include <cstdint>

#define NODES   50000
#define MAXE    800000
#define INDIM   128
#define HH      256     // HEADS*HIDDEN
#define HEADS   4
#define HID     64
#define EPSV    1e-5f
#define NEG     0.2f

// ---------------- PTX helpers (base sm_103-safe) ----------------
__device__ __forceinline__ uint32_t smem_to_u32(const void* p) {
    uint32_t a;
    asm("{ .reg .u64 t; cvta.to.shared.u64 t, %1; cvt.u32.u64 %0, t; }" : "=r"(a) : "l"(p));
    return a;
}
#define LDSM_X4(r0, r1, r2, r3, addr) \
    asm volatile("ldmatrix.sync.aligned.m8n8.x4.shared.b16 {%0,%1,%2,%3}, [%4];" \
        : "=r"(r0), "=r"(r1), "=r"(r2), "=r"(r3) : "r"(addr))
#define MMA_BF16(d, a, b) \
    asm volatile("mma.sync.aligned.m16n8k16.row.col.f32.bf16.bf16.f32 " \
        "{%0,%1,%2,%3}, {%4,%5,%6,%7}, {%8,%9}, {%0,%1,%2,%3};" \
        : "+f"((d)[0]), "+f"((d)[1]), "+f"((d)[2]), "+f"((d)[3]) \
        : "r"((a)[0]), "r"((a)[1]), "r"((a)[2]), "r"((a)[3]), "r"((b)[0]), "r"((b)[1]))

// -------- device scratch (no allocation allowed) --------
__device__ uint32_t g_hlh[NODES * 128];     // hl as packed half2 (cols 2i, 2i+1)
__device__ float g_agg[NODES * HH];
__device__ float g_asrc[NODES * HEADS];
__device__ float g_adst[NODES * HEADS];
__device__ float g_sums[512];
__device__ float g_scale[256];
__device__ float g_shift[256];
__device__ float g_mean[256];
__device__ float g_rowbias[256];
__device__ uint16_t g_Wt_hi[256 * 256];     // W^T split bf16 hi [n][k]
__device__ uint16_t g_Wt_lo[256 * 256];     // bf16 lo residual  [n][k]
__device__ uint16_t g_xh[NODES * INDIM];    // x split hi
__device__ uint16_t g_xl[NODES * INDIM];    // x split lo
__device__ uint16_t g_h2h[NODES * HH];      // post-BN2+ReLU split hi
__device__ uint16_t g_h2l[NODES * HH];      // split lo
// CSR build scratch
__device__ int g_deg[NODES];
__device__ int g_rowptr[NODES];
__device__ int g_cursor[NODES];
__device__ int g_bsums[256];
__device__ int g_csr[MAXE + NODES];

// ---------------- utility kernels (identical to R14 numerics) ----------------
__global__ void k_clear(float* __restrict__ p, int n) {
    int i = blockIdx.x * blockDim.x + threadIdx.x;
    if (i < n) p[i] = 0.f;
}

__global__ void k_colstats(const float* __restrict__ x, int n, int C,
                           float* __restrict__ sums, float* __restrict__ sumsq) {
    int c = threadIdx.x;
    float s = 0.f, s2 = 0.f;
    for (int r = blockIdx.x; r < n; r += gridDim.x) {
        float v = x[(size_t)r * C + c];
        s += v; s2 += v * v;
    }
    atomicAdd(&sums[c], s);
    atomicAdd(&sumsq[c], s2);
}

__global__ void k_bnfinal(const float* __restrict__ gamma, const float* __restrict__ beta,
                          int C, int n, int fold) {
    int c = threadIdx.x;
    if (c >= C) return;
    float mean = g_sums[c] / (float)n;
    float var  = g_sums[256 + c] / (float)n - mean * mean;
    float sc   = rsqrtf(var + EPSV) * gamma[c];
    g_scale[c] = sc;
    if (fold) g_shift[c] = beta[c] - mean * sc;
    else      g_mean[c]  = mean;
}

__global__ void k_rowbias(const float* __restrict__ W, int K) {
    __shared__ float sh[128];
    int j = blockIdx.x, t = threadIdx.x;
    float s = 0.f;
    for (int k = t; k < K; k += 128) s += g_shift[k] * W[(size_t)k * HH + j];
    sh[t] = s; __syncthreads();
    for (int off = 64; off; off >>= 1) { if (t < off) sh[t] += sh[t + off]; __syncthreads(); }
    if (t == 0) g_rowbias[j] = sh[0];
}

// ---------------- split helpers ----------------
__device__ __forceinline__ void splitf(float x, uint16_t& h, uint16_t& l) {
    __nv_bfloat16 bh = __float2bfloat16(x);
    float r = x - __bfloat162float(bh);
    __nv_bfloat16 bl = __float2bfloat16(r);
    h = __bfloat16_as_ushort(bh);
    l = __bfloat16_as_ushort(bl);
}

__global__ void k_prepw(const float* __restrict__ W, int K, const float* __restrict__ colscale) {
    int idx = blockIdx.x * blockDim.x + threadIdx.x;   // idx = n*K + k
    if (idx >= 256 * K) return;
    int n = idx / K, k = idx - n * K;
    float v = W[(size_t)k * 256 + n];
    if (colscale) v *= colscale[k];
    uint16_t h, l;
    splitf(v, h, l);
    g_Wt_hi[idx] = h;
    g_Wt_lo[idx] = l;
}

__global__ void k_prepx(const float* __restrict__ x, int total) {
    int i = blockIdx.x * blockDim.x + threadIdx.x;
    if (i >= total) return;
    uint16_t h, l;
    splitf(x[i], h, l);
    g_xh[i] = h;
    g_xl[i] = l;
}

// ---------------- HMMA GEMM (R14: static smem, sync staging, reg-pressure safe) --------
#define SPITCH 40

__global__ __launch_bounds__(256)
void k_mmagemm(const uint16_t* __restrict__ Ah, const uint16_t* __restrict__ Al,
               uint32_t* __restrict__ Chl, int M, int K,
               const float* __restrict__ rowbias,
               const float* __restrict__ atts, const float* __restrict__ attd) {
    __shared__ __align__(16) uint16_t As_hi[128 * SPITCH];
    __shared__ __align__(16) uint16_t As_lo[128 * SPITCH];
    __shared__ __align__(16) uint16_t Bs_hi[128 * SPITCH];
    __shared__ __align__(16) uint16_t Bs_lo[128 * SPITCH];

    const int tid = threadIdx.x, lane = tid & 31, wid = tid >> 5;
    const int warpM = wid >> 1, warpN = wid & 1;
    const int rowBase = blockIdx.y * 128;
    const int colBase = blockIdx.x * 128;

    const uint32_t sAh = smem_to_u32(As_hi), sAl = smem_to_u32(As_lo);
    const uint32_t sBh = smem_to_u32(Bs_hi), sBl = smem_to_u32(Bs_lo);

    float acc[2][8][4] = {};

    for (int k0 = 0; k0 < K; k0 += 32) {
        for (int i = tid; i < 128 * 8; i += 256) {
            int r = i >> 3, q = i & 7;
            int gr = rowBase + r;
            uint2 vh = make_uint2(0u, 0u), vl = make_uint2(0u, 0u);
            if (gr < M) {
                size_t gofs = (size_t)gr * K + k0 + q * 4;
                vh = *(const uint2*)(Ah + gofs);
                vl = *(const uint2*)(Al + gofs);
            }
            int off = r * SPITCH + q * 4;
            *(uint2*)(As_hi + off) = vh;
            *(uint2*)(As_lo + off) = vl;
        }
        for (int i = tid; i < 128 * 8; i += 256) {
            int n = i >> 3, q = i & 7;
            size_t gofs = (size_t)(colBase + n) * K + k0 + q * 4;
            uint2 vh = *(const uint2*)(g_Wt_hi + gofs);
            uint2 vl = *(const uint2*)(g_Wt_lo + gofs);
            int off = n * SPITCH + q * 4;
            *(uint2*)(Bs_hi + off) = vh;
            *(uint2*)(Bs_lo + off) = vl;
        }
        __syncthreads();

#pragma unroll
        for (int s = 0; s < 2; s++) {
            uint32_t ah[2][4], al[2][4];
#pragma unroll
            for (int mt = 0; mt < 2; mt++) {
                int rA = warpM * 32 + mt * 16 + (lane & 15);
                int kA = s * 16 + ((lane & 16) ? 8 : 0);
                uint32_t byteOff = (uint32_t)(rA * SPITCH + kA) * 2;
                LDSM_X4(ah[mt][0], ah[mt][1], ah[mt][2], ah[mt][3], sAh + byteOff);
                LDSM_X4(al[mt][0], al[mt][1], al[mt][2], al[mt][3], sAl + byteOff);
            }
            uint32_t bh[8][2], bl[8][2];
#pragma unroll
            for (int p = 0; p < 4; p++) {
                int g = lane >> 3;
                int nB = warpN * 64 + p * 16 + ((g & 2) ? 8 : 0) + (lane & 7);
                int kB = s * 16 + ((g & 1) ? 8 : 0);
                uint32_t byteOff = (uint32_t)(nB * SPITCH + kB) * 2;
                LDSM_X4(bh[2*p][0], bh[2*p][1], bh[2*p+1][0], bh[2*p+1][1], sBh + byteOff);
                LDSM_X4(bl[2*p][0], bl[2*p][1], bl[2*p+1][0], bl[2*p+1][1], sBl + byteOff);
            }
#pragma unroll
            for (int mt = 0; mt < 2; mt++)
#pragma unroll
                for (int nt = 0; nt < 8; nt++) {
                    MMA_BF16(acc[mt][nt], ah[mt], bh[nt]);
                    MMA_BF16(acc[mt][nt], ah[mt], bl[nt]);
                    MMA_BF16(acc[mt][nt], al[mt], bh[nt]);
                }
        }
        __syncthreads();
    }

    // ---- epilogue: rowbias, half2 store, fused attention dots ----
    if (rowbias) {
#pragma unroll
        for (int nt = 0; nt < 8; nt++) {
            int col = colBase + warpN * 64 + nt * 8 + (lane & 3) * 2;
            float b0 = rowbias[col], b1 = rowbias[col + 1];
#pragma unroll
            for (int mt = 0; mt < 2; mt++) {
                acc[mt][nt][0] += b0; acc[mt][nt][1] += b1;
                acc[mt][nt][2] += b0; acc[mt][nt][3] += b1;
            }
        }
    }
#pragma unroll
    for (int mt = 0; mt < 2; mt++) {
        int r0 = rowBase + warpM * 32 + mt * 16 + (lane >> 2);
#pragma unroll
        for (int half = 0; half < 2; half++) {
            int row = r0 + half * 8;
            if (row >= M) continue;
#pragma unroll
            for (int nt = 0; nt < 8; nt++) {
                int col = colBase + warpN * 64 + nt * 8 + (lane & 3) * 2;  // even
                __half2 hv = __floats2half2_rn(acc[mt][nt][half * 2], acc[mt][nt][half * 2 + 1]);
                Chl[(size_t)row * 128 + (col >> 1)] = *(uint32_t*)&hv;
            }
        }
    }
    // attention dots from fp32 accumulators (head h = this warp's 64-col span)
    {
        int h = (colBase >> 6) + warpN;
        const float* As_v = atts + h * 64;
        const float* Ad_v = attd + h * 64;
#pragma unroll
        for (int mt = 0; mt < 2; mt++) {
#pragma unroll
            for (int half = 0; half < 2; half++) {
                float ds = 0.f, dd = 0.f;
#pragma unroll
                for (int nt = 0; nt < 8; nt++) {
                    int cw = nt * 8 + (lane & 3) * 2;
                    float v0 = acc[mt][nt][half * 2], v1 = acc[mt][nt][half * 2 + 1];
                    ds += v0 * As_v[cw] + v1 * As_v[cw + 1];
                    dd += v0 * Ad_v[cw] + v1 * Ad_v[cw + 1];
                }
                ds += __shfl_xor_sync(0xffffffffu, ds, 1);
                ds += __shfl_xor_sync(0xffffffffu, ds, 2);
                dd += __shfl_xor_sync(0xffffffffu, dd, 1);
                dd += __shfl_xor_sync(0xffffffffu, dd, 2);
                int row = rowBase + warpM * 32 + mt * 16 + half * 8 + (lane >> 2);
                if ((lane & 3) == 0 && row < M) {
                    g_asrc[row * HEADS + h] = ds;
                    g_adst[row * HEADS + h] = dd;
                }
            }
        }
    }
}

// ---------------- CSR build ----------------
__global__ void k_deginit(int n) {
    int i = blockIdx.x * blockDim.x + threadIdx.x;
    if (i < n) g_deg[i] = 1;
}
__global__ void k_hist(const int* __restrict__ dstp, int E) {
    int i = blockIdx.x * blockDim.x + threadIdx.x;
    if (i < E) atomicAdd(&g_deg[dstp[i]], 1);
}
__global__ void k_scan1(int n) {
    __shared__ int sh[256];
    int tid = threadIdx.x;
    int i = blockIdx.x * 256 + tid;
    int v = (i < n) ? g_deg[i] : 0;
    sh[tid] = v; __syncthreads();
    for (int off = 1; off < 256; off <<= 1) {
        int t = (tid >= off) ? sh[tid - off] : 0;
        __syncthreads();
        sh[tid] += t;
        __syncthreads();
    }
    if (i < n) g_rowptr[i] = sh[tid] - v;
    if (tid == 255) g_bsums[blockIdx.x] = sh[255];
}
__global__ void k_scan2(int nb) {
    __shared__ int sh[256];
    int tid = threadIdx.x;
    int v = (tid < nb) ? g_bsums[tid] : 0;
    sh[tid] = v; __syncthreads();
    for (int off = 1; off < 256; off <<= 1) {
        int t = (tid >= off) ? sh[tid - off] : 0;
        __syncthreads();
        sh[tid] += t;
        __syncthreads();
    }
    if (tid < nb) g_bsums[tid] = sh[tid] - v;
}
__global__ void k_scan3(int n) {
    int i = blockIdx.x * 256 + threadIdx.x;
    if (i < n) {
        int r = g_rowptr[i] + g_bsums[blockIdx.x];
        g_rowptr[i] = r;
        g_cursor[i] = r;
    }
}
__global__ void k_scatter(const int* __restrict__ srcp, const int* __restrict__ dstp,
                          int E, int n) {
    int i = blockIdx.x * blockDim.x + threadIdx.x;
    int Et = E + n;
    if (i >= Et) return;
    int s, d;
    if (i < E) { s = srcp[i]; d = dstp[i]; }
    else       { s = d = i - E; }
    int pos = atomicAdd(&g_cursor[d], 1);
    g_csr[pos] = s;
}

// ---------------- gather aggregation: warp per dst node, fp16 features ----------------
template <int LAYER>
__global__ void k_gather(const float* __restrict__ bias, float* __restrict__ out, int n) {
    int d = (blockIdx.x * blockDim.x + threadIdx.x) >> 5;
    int lane = threadIdx.x & 31;
    if (d >= n) return;

    float adv = 0.f;
    if (lane < HEADS) adv = g_adst[d * HEADS + lane];

    int e   = g_rowptr[d];
    int end = g_cursor[d];

    float acc[8] = {};
    float den = 0.f;
#pragma unroll 2
    for (; e < end; e++) {
        int s = g_csr[e];
        float wl = 0.f;
        if (lane < HEADS) {
            float a = g_asrc[s * HEADS + lane] + adv;
            a = (a > 0.f) ? a : NEG * a;
            wl = __expf(a);
            den += wl;
        }
        const uint32_t* hr = g_hlh + (size_t)s * 128;
#pragma unroll
        for (int h = 0; h < HEADS; h++) {
            float wh = __shfl_sync(0xffffffffu, wl, h);
            uint32_t p = __ldg(hr + h * 32 + lane);
            float2 f = __half22float2(*(__half2*)&p);
            acc[2*h]   += wh * f.x;
            acc[2*h+1] += wh * f.y;
        }
    }
    float dv[4];
#pragma unroll
    for (int h = 0; h < HEADS; h++) dv[h] = __shfl_sync(0xffffffffu, den, h);

    if (LAYER == 1) {
        float* orow = g_agg + (size_t)d * HH;
#pragma unroll
        for (int h = 0; h < HEADS; h++) {
            int c0 = h * 64 + 2 * lane;
            orow[c0]     = acc[2*h]   / dv[h] + bias[c0];
            orow[c0 + 1] = acc[2*h+1] / dv[h] + bias[c0 + 1];
        }
    } else {
        float v0 = 0.f, v1 = 0.f;
#pragma unroll
        for (int h = 0; h < HEADS; h++) {
            v0 += acc[2*h]   / dv[h];
            v1 += acc[2*h+1] / dv[h];
        }
        int c0 = 2 * lane;
        out[d * HID + c0]     = 0.25f * v0 + bias[c0];
        out[d * HID + c0 + 1] = 0.25f * v1 + bias[c0 + 1];
    }
}

// BN2 normalize + ReLU -> split bf16 (feeds GEMM2 directly)
__global__ void k_bnrelu(const float* __restrict__ beta, int n) {
    size_t i = (size_t)blockIdx.x * blockDim.x + threadIdx.x;
    if (i >= (size_t)n * HH) return;
    int c = (int)(i & 255);
    float v = (g_agg[i] - g_mean[c]) * g_scale[c] + beta[c];
    v = (v > 0.f) ? v : 0.f;
    uint16_t h, l;
    splitf(v, h, l);
    g_h2h[i] = h;
    g_h2l[i] = l;
}

// ---------------- host launcher: fork/join graph branches ----------------
extern "C" void kernel_launch(void* const* d_in, const int* in_sizes, int n_in,
                              void* d_out, int out_size) {
    const float* x        = (const float*)d_in[0];
    const int*   ei       = (const int*)d_in[1];      // int32 (JAX x64 disabled)
    const float* gamma1   = (const float*)d_in[2];
    const float* beta1    = (const float*)d_in[3];
    const float* W1       = (const float*)d_in[4];
    const float* att_src1 = (const float*)d_in[5];
    const float* att_dst1 = (const float*)d_in[6];
    const float* bias1    = (const float*)d_in[7];
    const float* gamma2   = (const float*)d_in[8];
    const float* beta2    = (const float*)d_in[9];
    const float* W2       = (const float*)d_in[10];
    const float* att_src2 = (const float*)d_in[11];
    const float* att_dst2 = (const float*)d_in[12];
    const float* bias2    = (const float*)d_in[13];

    int n = in_sizes[0] / INDIM;
    int E = in_sizes[1] / 2;
    const int* srcp = ei;
    const int* dstp = ei + E;
    float* out = (float*)d_out;

    float *p_agg, *p_sums, *p_scale;
    cudaGetSymbolAddress((void**)&p_agg,  g_agg);
    cudaGetSymbolAddress((void**)&p_sums, g_sums);
    cudaGetSymbolAddress((void**)&p_scale, g_scale);
    uint32_t* p_hlh;
    cudaGetSymbolAddress((void**)&p_hlh, g_hlh);
    uint16_t *p_xh, *p_xl, *p_h2h, *p_h2l;
    cudaGetSymbolAddress((void**)&p_xh,  g_xh);
    cudaGetSymbolAddress((void**)&p_xl,  g_xl);
    cudaGetSymbolAddress((void**)&p_h2h, g_h2h);
    cudaGetSymbolAddress((void**)&p_h2l, g_h2l);

    int Et = E + n;
    int featElems = n * HH;
    int scanBlocks = (n + 255) / 256;
    dim3 gemmGrid(2, (n + 127) / 128);

    // side stream + fork/join events (created per call; graph capture turns these
    // into parallel graph branches). Not destroyed: destroy during active capture
    // of the origin stream is unsafe; a few leaked handles per process are harmless.
    cudaStream_t s2;
    cudaStreamCreateWithFlags(&s2, cudaStreamNonBlocking);
    cudaEvent_t eF1, eJ1, eF2, eJ2;
    cudaEventCreateWithFlags(&eF1, cudaEventDisableTiming);
    cudaEventCreateWithFlags(&eJ1, cudaEventDisableTiming);
    cudaEventCreateWithFlags(&eF2, cudaEventDisableTiming);
    cudaEventCreateWithFlags(&eJ2, cudaEventDisableTiming);

    // ---- fork: CSR build on side stream (independent until k_gather<1>) ----
    cudaEventRecord(eF1, 0);
    cudaStreamWaitEvent(s2, eF1, 0);
    k_deginit<<<scanBlocks, 256, 0, s2>>>(n);
    k_hist<<<(E + 255) / 256, 256, 0, s2>>>(dstp, E);
    k_scan1<<<scanBlocks, 256, 0, s2>>>(n);
    k_scan2<<<1, 256, 0, s2>>>(scanBlocks);
    k_scan3<<<scanBlocks, 256, 0, s2>>>(n);
    k_scatter<<<(Et + 255) / 256, 256, 0, s2>>>(srcp, dstp, E, n);
    cudaEventRecord(eJ1, s2);

    // ---- main: BN1 stats + fold + prep + GEMM1 ----
    k_clear<<<2, 256>>>(p_sums, 512);
    k_colstats<<<512, INDIM>>>(x, n, INDIM, p_sums, p_sums + 256);
    k_bnfinal<<<1, INDIM>>>(gamma1, beta1, INDIM, n, 1);
    k_rowbias<<<HH, 128>>>(W1, INDIM);
    k_prepx<<<(n * INDIM + 255) / 256, 256>>>(x, n * INDIM);
    k_prepw<<<(256 * INDIM + 255) / 256, 256>>>(W1, INDIM, p_scale);
    k_mmagemm<<<gemmGrid, 256>>>(p_xh, p_xl, p_hlh, n, INDIM,
                                 g_rowbias, att_src1, att_dst1);

    // ---- join CSR branch, then gather1 ----
    cudaStreamWaitEvent(0, eJ1, 0);
    k_gather<1><<<(n * 32 + 255) / 256, 256>>>(bias1, nullptr, n);

    // ---- fork: W2 prep on side stream (independent of BN2 chain) ----
    cudaEventRecord(eF2, 0);
    cudaStreamWaitEvent(s2, eF2, 0);
    k_prepw<<<(256 * HH + 255) / 256, 256, 0, s2>>>(W2, HH, nullptr);
    cudaEventRecord(eJ2, s2);

    // ---- main: BN2 stats + normalize+ReLU -> split bf16 ----
    k_clear<<<2, 256>>>(p_sums, 512);
    k_colstats<<<512, HH>>>(p_agg, n, HH, p_sums, p_sums + 256);
    k_bnfinal<<<1, HH>>>(gamma2, beta2, HH, n, 0);
    k_bnrelu<<<(featElems + 255) / 256, 256>>>(beta2, n);

    // ---- join W2 branch, then GEMM2 + gather2 ----
    cudaStreamWaitEvent(0, eJ2, 0);
    k_mmagemm<<<gemmGrid, 256>>>(p_h2h, p_h2l, p_hlh, n, HH,
                                 nullptr, att_src2, att_dst2);
    k_gather<2><<<(n * 32 + 255) / 256, 256>>>(bias2, out, n);
}

// round 17
// speedup vs baseline: 1.4527x; 1.0482x over previous
#include <cuda_runtime.h>
#include <cuda_bf16.h>
#include <cuda_fp16.h>
#include <cstdint>

#define NODES   50000
#define MAXE    800000
#define INDIM   128
#define HH      256     // HEADS*HIDDEN
#define HEADS   4
#define HID     64
#define EPSV    1e-5f
#define NEG     0.2f

// ---------------- PTX helpers (base sm_103-safe) ----------------
__device__ __forceinline__ uint32_t smem_to_u32(const void* p) {
    uint32_t a;
    asm("{ .reg .u64 t; cvta.to.shared.u64 t, %1; cvt.u32.u64 %0, t; }" : "=r"(a) : "l"(p));
    return a;
}
#define LDSM_X4(r0, r1, r2, r3, addr) \
    asm volatile("ldmatrix.sync.aligned.m8n8.x4.shared.b16 {%0,%1,%2,%3}, [%4];" \
        : "=r"(r0), "=r"(r1), "=r"(r2), "=r"(r3) : "r"(addr))
#define MMA_BF16(d, a, b) \
    asm volatile("mma.sync.aligned.m16n8k16.row.col.f32.bf16.bf16.f32 " \
        "{%0,%1,%2,%3}, {%4,%5,%6,%7}, {%8,%9}, {%0,%1,%2,%3};" \
        : "+f"((d)[0]), "+f"((d)[1]), "+f"((d)[2]), "+f"((d)[3]) \
        : "r"((a)[0]), "r"((a)[1]), "r"((a)[2]), "r"((a)[3]), "r"((b)[0]), "r"((b)[1]))

// -------- device scratch (no allocation allowed) --------
__device__ uint32_t g_hlh[NODES * 128];     // hl as packed half2 (cols 2i, 2i+1)
__device__ float g_agg[NODES * HH];
__device__ float g_asrc[NODES * HEADS];
__device__ float g_adst[NODES * HEADS];
__device__ float g_sums[1024];              // [0:256) s1 [256:512) sq1 [512:768) s2 [768:1024) sq2
__device__ float g_scale[256];
__device__ float g_mean[256];
__device__ float g_rowbias[256];
__device__ uint16_t g_Wt_hi[256 * 256];     // W^T split bf16 hi [n][k]
__device__ uint16_t g_Wt_lo[256 * 256];     // bf16 lo residual  [n][k]
__device__ uint16_t g_xh[NODES * INDIM];    // x split hi
__device__ uint16_t g_xl[NODES * INDIM];    // x split lo
__device__ uint16_t g_h2h[NODES * HH];      // post-BN2+ReLU split hi
__device__ uint16_t g_h2l[NODES * HH];      // split lo
// CSR build scratch
__device__ int g_deg[NODES];
__device__ int g_rowptr[NODES];
__device__ int g_cursor[NODES];
__device__ int g_bsums[256];
__device__ int g_csr[MAXE + NODES];

// ---------------- utility kernels ----------------
__global__ void k_clear(float* __restrict__ p, int n) {
    int i = blockIdx.x * blockDim.x + threadIdx.x;
    if (i < n) p[i] = 0.f;
}

// ---------------- split helpers ----------------
__device__ __forceinline__ void splitf(float x, uint16_t& h, uint16_t& l) {
    __nv_bfloat16 bh = __float2bfloat16(x);
    float r = x - __bfloat162float(bh);
    __nv_bfloat16 bl = __float2bfloat16(r);
    h = __bfloat16_as_ushort(bh);
    l = __bfloat16_as_ushort(bl);
}

// fused: BN1 column stats + x split (reads x once)
__global__ void k_prepx_stats(const float* __restrict__ x, int n) {
    int c = threadIdx.x;          // 128 threads = INDIM columns
    float s = 0.f, s2 = 0.f;
    for (int r = blockIdx.x; r < n; r += gridDim.x) {
        size_t idx = (size_t)r * INDIM + c;
        float v = x[idx];
        s += v; s2 += v * v;
        uint16_t h, l;
        splitf(v, h, l);
        g_xh[idx] = h;
        g_xl[idx] = l;
    }
    atomicAdd(&g_sums[c], s);
    atomicAdd(&g_sums[256 + c], s2);
}

// BN1 finalize + fold: scale + rank-1 rowbias, one kernel (grid=256 cols, 128 thr)
__global__ void k_bn1fold(const float* __restrict__ gamma, const float* __restrict__ beta,
                          const float* __restrict__ W, int n) {
    __shared__ float ssh[128];
    __shared__ float red[128];
    int j = blockIdx.x, t = threadIdx.x;
    float mean = g_sums[t] / (float)n;
    float var  = g_sums[256 + t] / (float)n - mean * mean;
    float sc   = rsqrtf(var + EPSV) * gamma[t];
    ssh[t] = beta[t] - mean * sc;
    if (j == 0) g_scale[t] = sc;          // consumed by k_prepw (launched after)
    __syncthreads();
    red[t] = ssh[t] * W[(size_t)t * HH + j];
    __syncthreads();
    for (int off = 64; off; off >>= 1) { if (t < off) red[t] += red[t + off]; __syncthreads(); }
    if (t == 0) g_rowbias[j] = red[0];
}

// BN2 finalize: mean + scale from slots
__global__ void k_bnfinal2(const float* __restrict__ gamma,
                           const float* __restrict__ sums, const float* __restrict__ sumsq,
                           int n) {
    int c = threadIdx.x;
    float mean = sums[c] / (float)n;
    float var  = sumsq[c] / (float)n - mean * mean;
    g_scale[c] = rsqrtf(var + EPSV) * gamma[c];
    g_mean[c]  = mean;
}

__global__ void k_colstats(const float* __restrict__ x, int n, int C,
                           float* __restrict__ sums, float* __restrict__ sumsq) {
    int c = threadIdx.x;
    float s = 0.f, s2 = 0.f;
    for (int r = blockIdx.x; r < n; r += gridDim.x) {
        float v = x[(size_t)r * C + c];
        s += v; s2 += v * v;
    }
    atomicAdd(&sums[c], s);
    atomicAdd(&sumsq[c], s2);
}

__global__ void k_prepw(const float* __restrict__ W, int K, const float* __restrict__ colscale) {
    int idx = blockIdx.x * blockDim.x + threadIdx.x;   // idx = n*K + k
    if (idx >= 256 * K) return;
    int n = idx / K, k = idx - n * K;
    float v = W[(size_t)k * 256 + n];
    if (colscale) v *= colscale[k];
    uint16_t h, l;
    splitf(v, h, l);
    g_Wt_hi[idx] = h;
    g_Wt_lo[idx] = l;
}

// ---------------- HMMA GEMM (R14: static smem, sync staging, reg-pressure safe) --------
#define SPITCH 40

__global__ __launch_bounds__(256)
void k_mmagemm(const uint16_t* __restrict__ Ah, const uint16_t* __restrict__ Al,
               uint32_t* __restrict__ Chl, int M, int K,
               const float* __restrict__ rowbias,
               const float* __restrict__ atts, const float* __restrict__ attd) {
    __shared__ __align__(16) uint16_t As_hi[128 * SPITCH];
    __shared__ __align__(16) uint16_t As_lo[128 * SPITCH];
    __shared__ __align__(16) uint16_t Bs_hi[128 * SPITCH];
    __shared__ __align__(16) uint16_t Bs_lo[128 * SPITCH];

    const int tid = threadIdx.x, lane = tid & 31, wid = tid >> 5;
    const int warpM = wid >> 1, warpN = wid & 1;
    const int rowBase = blockIdx.y * 128;
    const int colBase = blockIdx.x * 128;

    const uint32_t sAh = smem_to_u32(As_hi), sAl = smem_to_u32(As_lo);
    const uint32_t sBh = smem_to_u32(Bs_hi), sBl = smem_to_u32(Bs_lo);

    float acc[2][8][4] = {};

    for (int k0 = 0; k0 < K; k0 += 32) {
        for (int i = tid; i < 128 * 8; i += 256) {
            int r = i >> 3, q = i & 7;
            int gr = rowBase + r;
            uint2 vh = make_uint2(0u, 0u), vl = make_uint2(0u, 0u);
            if (gr < M) {
                size_t gofs = (size_t)gr * K + k0 + q * 4;
                vh = *(const uint2*)(Ah + gofs);
                vl = *(const uint2*)(Al + gofs);
            }
            int off = r * SPITCH + q * 4;
            *(uint2*)(As_hi + off) = vh;
            *(uint2*)(As_lo + off) = vl;
        }
        for (int i = tid; i < 128 * 8; i += 256) {
            int n = i >> 3, q = i & 7;
            size_t gofs = (size_t)(colBase + n) * K + k0 + q * 4;
            uint2 vh = *(const uint2*)(g_Wt_hi + gofs);
            uint2 vl = *(const uint2*)(g_Wt_lo + gofs);
            int off = n * SPITCH + q * 4;
            *(uint2*)(Bs_hi + off) = vh;
            *(uint2*)(Bs_lo + off) = vl;
        }
        __syncthreads();

#pragma unroll
        for (int s = 0; s < 2; s++) {
            uint32_t ah[2][4], al[2][4];
#pragma unroll
            for (int mt = 0; mt < 2; mt++) {
                int rA = warpM * 32 + mt * 16 + (lane & 15);
                int kA = s * 16 + ((lane & 16) ? 8 : 0);
                uint32_t byteOff = (uint32_t)(rA * SPITCH + kA) * 2;
                LDSM_X4(ah[mt][0], ah[mt][1], ah[mt][2], ah[mt][3], sAh + byteOff);
                LDSM_X4(al[mt][0], al[mt][1], al[mt][2], al[mt][3], sAl + byteOff);
            }
            uint32_t bh[8][2], bl[8][2];
#pragma unroll
            for (int p = 0; p < 4; p++) {
                int g = lane >> 3;
                int nB = warpN * 64 + p * 16 + ((g & 2) ? 8 : 0) + (lane & 7);
                int kB = s * 16 + ((g & 1) ? 8 : 0);
                uint32_t byteOff = (uint32_t)(nB * SPITCH + kB) * 2;
                LDSM_X4(bh[2*p][0], bh[2*p][1], bh[2*p+1][0], bh[2*p+1][1], sBh + byteOff);
                LDSM_X4(bl[2*p][0], bl[2*p][1], bl[2*p+1][0], bl[2*p+1][1], sBl + byteOff);
            }
#pragma unroll
            for (int mt = 0; mt < 2; mt++)
#pragma unroll
                for (int nt = 0; nt < 8; nt++) {
                    MMA_BF16(acc[mt][nt], ah[mt], bh[nt]);
                    MMA_BF16(acc[mt][nt], ah[mt], bl[nt]);
                    MMA_BF16(acc[mt][nt], al[mt], bh[nt]);
                }
        }
        __syncthreads();
    }

    // ---- epilogue: rowbias, half2 store, fused attention dots ----
    if (rowbias) {
#pragma unroll
        for (int nt = 0; nt < 8; nt++) {
            int col = colBase + warpN * 64 + nt * 8 + (lane & 3) * 2;
            float b0 = rowbias[col], b1 = rowbias[col + 1];
#pragma unroll
            for (int mt = 0; mt < 2; mt++) {
                acc[mt][nt][0] += b0; acc[mt][nt][1] += b1;
                acc[mt][nt][2] += b0; acc[mt][nt][3] += b1;
            }
        }
    }
#pragma unroll
    for (int mt = 0; mt < 2; mt++) {
        int r0 = rowBase + warpM * 32 + mt * 16 + (lane >> 2);
#pragma unroll
        for (int half = 0; half < 2; half++) {
            int row = r0 + half * 8;
            if (row >= M) continue;
#pragma unroll
            for (int nt = 0; nt < 8; nt++) {
                int col = colBase + warpN * 64 + nt * 8 + (lane & 3) * 2;  // even
                __half2 hv = __floats2half2_rn(acc[mt][nt][half * 2], acc[mt][nt][half * 2 + 1]);
                Chl[(size_t)row * 128 + (col >> 1)] = *(uint32_t*)&hv;
            }
        }
    }
    // attention dots from fp32 accumulators (head h = this warp's 64-col span)
    {
        int h = (colBase >> 6) + warpN;
        const float* As_v = atts + h * 64;
        const float* Ad_v = attd + h * 64;
#pragma unroll
        for (int mt = 0; mt < 2; mt++) {
#pragma unroll
            for (int half = 0; half < 2; half++) {
                float ds = 0.f, dd = 0.f;
#pragma unroll
                for (int nt = 0; nt < 8; nt++) {
                    int cw = nt * 8 + (lane & 3) * 2;
                    float v0 = acc[mt][nt][half * 2], v1 = acc[mt][nt][half * 2 + 1];
                    ds += v0 * As_v[cw] + v1 * As_v[cw + 1];
                    dd += v0 * Ad_v[cw] + v1 * Ad_v[cw + 1];
                }
                ds += __shfl_xor_sync(0xffffffffu, ds, 1);
                ds += __shfl_xor_sync(0xffffffffu, ds, 2);
                dd += __shfl_xor_sync(0xffffffffu, dd, 1);
                dd += __shfl_xor_sync(0xffffffffu, dd, 2);
                int row = rowBase + warpM * 32 + mt * 16 + half * 8 + (lane >> 2);
                if ((lane & 3) == 0 && row < M) {
                    g_asrc[row * HEADS + h] = ds;
                    g_adst[row * HEADS + h] = dd;
                }
            }
        }
    }
}

// ---------------- CSR build ----------------
__global__ void k_deginit(int n) {
    int i = blockIdx.x * blockDim.x + threadIdx.x;
    if (i < n) g_deg[i] = 1;
}
__global__ void k_hist(const int* __restrict__ dstp, int E) {
    int i = blockIdx.x * blockDim.x + threadIdx.x;
    if (i < E) atomicAdd(&g_deg[dstp[i]], 1);
}
__global__ void k_scan1(int n) {
    __shared__ int sh[256];
    int tid = threadIdx.x;
    int i = blockIdx.x * 256 + tid;
    int v = (i < n) ? g_deg[i] : 0;
    sh[tid] = v; __syncthreads();
    for (int off = 1; off < 256; off <<= 1) {
        int t = (tid >= off) ? sh[tid - off] : 0;
        __syncthreads();
        sh[tid] += t;
        __syncthreads();
    }
    if (i < n) g_rowptr[i] = sh[tid] - v;
    if (tid == 255) g_bsums[blockIdx.x] = sh[255];
}
__global__ void k_scan2(int nb) {
    __shared__ int sh[256];
    int tid = threadIdx.x;
    int v = (tid < nb) ? g_bsums[tid] : 0;
    sh[tid] = v; __syncthreads();
    for (int off = 1; off < 256; off <<= 1) {
        int t = (tid >= off) ? sh[tid - off] : 0;
        __syncthreads();
        sh[tid] += t;
        __syncthreads();
    }
    if (tid < nb) g_bsums[tid] = sh[tid] - v;
}
__global__ void k_scan3(int n) {
    int i = blockIdx.x * 256 + threadIdx.x;
    if (i < n) {
        int r = g_rowptr[i] + g_bsums[blockIdx.x];
        g_rowptr[i] = r;
        g_cursor[i] = r;
    }
}
__global__ void k_scatter(const int* __restrict__ srcp, const int* __restrict__ dstp,
                          int E, int n) {
    int i = blockIdx.x * blockDim.x + threadIdx.x;
    int Et = E + n;
    if (i >= Et) return;
    int s, d;
    if (i < E) { s = srcp[i]; d = dstp[i]; }
    else       { s = d = i - E; }
    int pos = atomicAdd(&g_cursor[d], 1);
    g_csr[pos] = s;
}

// ---------------- gather: warp per dst node, one uint4 (8 fp16 cols) per lane ---------
// lane l owns cols [8l, 8l+8) of the 256-wide row; head = l>>3.
template <int LAYER>
__global__ void k_gather(const float* __restrict__ bias, float* __restrict__ out, int n) {
    int d = (blockIdx.x * blockDim.x + threadIdx.x) >> 5;
    int lane = threadIdx.x & 31;
    if (d >= n) return;

    float adv = 0.f;
    if (lane < HEADS) adv = g_adst[d * HEADS + lane];
    const int myhead = lane >> 3;

    int e   = g_rowptr[d];
    int end = g_cursor[d];

    float acc[8] = {};
    float den = 0.f;
#pragma unroll 2
    for (; e < end; e++) {
        int s = g_csr[e];
        float wl = 0.f;
        if (lane < HEADS) {
            float a = g_asrc[s * HEADS + lane] + adv;
            a = (a > 0.f) ? a : NEG * a;
            wl = __expf(a);
            den += wl;
        }
        float wh = __shfl_sync(0xffffffffu, wl, myhead);
        uint4 p = __ldg((const uint4*)(g_hlh + (size_t)s * 128) + lane);
        float2 f0 = __half22float2(*(__half2*)&p.x);
        float2 f1 = __half22float2(*(__half2*)&p.y);
        float2 f2 = __half22float2(*(__half2*)&p.z);
        float2 f3 = __half22float2(*(__half2*)&p.w);
        acc[0] += wh * f0.x; acc[1] += wh * f0.y;
        acc[2] += wh * f1.x; acc[3] += wh * f1.y;
        acc[4] += wh * f2.x; acc[5] += wh * f2.y;
        acc[6] += wh * f3.x; acc[7] += wh * f3.y;
    }
    float dv = __shfl_sync(0xffffffffu, den, myhead);

    if (LAYER == 1) {
        int c0 = lane * 8;
        float* orow = g_agg + (size_t)d * HH + c0;
        float4 o0 = make_float4(acc[0] / dv + bias[c0],     acc[1] / dv + bias[c0 + 1],
                                acc[2] / dv + bias[c0 + 2], acc[3] / dv + bias[c0 + 3]);
        float4 o1 = make_float4(acc[4] / dv + bias[c0 + 4], acc[5] / dv + bias[c0 + 5],
                                acc[6] / dv + bias[c0 + 6], acc[7] / dv + bias[c0 + 7]);
        *(float4*)orow = o0;
        *(float4*)(orow + 4) = o1;
    } else {
#pragma unroll
        for (int j = 0; j < 8; j++) {
            acc[j] /= dv;
            acc[j] += __shfl_xor_sync(0xffffffffu, acc[j], 8);
            acc[j] += __shfl_xor_sync(0xffffffffu, acc[j], 16);
        }
        if (lane < 8) {
            int c0 = lane * 8;
            float* orow = out + (size_t)d * HID + c0;
#pragma unroll
            for (int j = 0; j < 8; j++) orow[j] = 0.25f * acc[j] + bias[c0 + j];
        }
    }
}

// BN2 normalize + ReLU -> split bf16 (feeds GEMM2 directly)
__global__ void k_bnrelu(const float* __restrict__ beta, int n) {
    size_t i = (size_t)blockIdx.x * blockDim.x + threadIdx.x;
    if (i >= (size_t)n * HH) return;
    int c = (int)(i & 255);
    float v = (g_agg[i] - g_mean[c]) * g_scale[c] + beta[c];
    v = (v > 0.f) ? v : 0.f;
    uint16_t h, l;
    splitf(v, h, l);
    g_h2h[i] = h;
    g_h2l[i] = l;
}

// ---------------- host launcher: fork/join graph branches ----------------
extern "C" void kernel_launch(void* const* d_in, const int* in_sizes, int n_in,
                              void* d_out, int out_size) {
    const float* x        = (const float*)d_in[0];
    const int*   ei       = (const int*)d_in[1];      // int32 (JAX x64 disabled)
    const float* gamma1   = (const float*)d_in[2];
    const float* beta1    = (const float*)d_in[3];
    const float* W1       = (const float*)d_in[4];
    const float* att_src1 = (const float*)d_in[5];
    const float* att_dst1 = (const float*)d_in[6];
    const float* bias1    = (const float*)d_in[7];
    const float* gamma2   = (const float*)d_in[8];
    const float* beta2    = (const float*)d_in[9];
    const float* W2       = (const float*)d_in[10];
    const float* att_src2 = (const float*)d_in[11];
    const float* att_dst2 = (const float*)d_in[12];
    const float* bias2    = (const float*)d_in[13];

    int n = in_sizes[0] / INDIM;
    int E = in_sizes[1] / 2;
    const int* srcp = ei;
    const int* dstp = ei + E;
    float* out = (float*)d_out;

    float *p_agg, *p_sums, *p_scale;
    cudaGetSymbolAddress((void**)&p_agg,  g_agg);
    cudaGetSymbolAddress((void**)&p_sums, g_sums);
    cudaGetSymbolAddress((void**)&p_scale, g_scale);
    uint32_t* p_hlh;
    cudaGetSymbolAddress((void**)&p_hlh, g_hlh);
    uint16_t *p_xh, *p_xl, *p_h2h, *p_h2l;
    cudaGetSymbolAddress((void**)&p_xh,  g_xh);
    cudaGetSymbolAddress((void**)&p_xl,  g_xl);
    cudaGetSymbolAddress((void**)&p_h2h, g_h2h);
    cudaGetSymbolAddress((void**)&p_h2l, g_h2l);

    int Et = E + n;
    int featElems = n * HH;
    int scanBlocks = (n + 255) / 256;
    dim3 gemmGrid(2, (n + 127) / 128);

    // side stream + fork/join events (created per call; graph capture turns these
    // into parallel branches; handles deliberately not destroyed during capture)
    cudaStream_t s2;
    cudaStreamCreateWithFlags(&s2, cudaStreamNonBlocking);
    cudaEvent_t eF1, eJ1, eF2, eJ2;
    cudaEventCreateWithFlags(&eF1, cudaEventDisableTiming);
    cudaEventCreateWithFlags(&eJ1, cudaEventDisableTiming);
    cudaEventCreateWithFlags(&eF2, cudaEventDisableTiming);
    cudaEventCreateWithFlags(&eJ2, cudaEventDisableTiming);

    // ---- fork: CSR build on side stream (independent until k_gather<1>) ----
    cudaEventRecord(eF1, 0);
    cudaStreamWaitEvent(s2, eF1, 0);
    k_deginit<<<scanBlocks, 256, 0, s2>>>(n);
    k_hist<<<(E + 255) / 256, 256, 0, s2>>>(dstp, E);
    k_scan1<<<scanBlocks, 256, 0, s2>>>(n);
    k_scan2<<<1, 256, 0, s2>>>(scanBlocks);
    k_scan3<<<scanBlocks, 256, 0, s2>>>(n);
    k_scatter<<<(Et + 255) / 256, 256, 0, s2>>>(srcp, dstp, E, n);
    cudaEventRecord(eJ1, s2);

    // ---- main: BN1 stats fused with x split, fold, W1 prep, GEMM1 ----
    k_clear<<<4, 256>>>(p_sums, 1024);
    k_prepx_stats<<<512, INDIM>>>(x, n);
    k_bn1fold<<<HH, 128>>>(gamma1, beta1, W1, n);
    k_prepw<<<(256 * INDIM + 255) / 256, 256>>>(W1, INDIM, p_scale);
    k_mmagemm<<<gemmGrid, 256>>>(p_xh, p_xl, p_hlh, n, INDIM,
                                 g_rowbias, att_src1, att_dst1);

    // ---- fork: W2 prep on side stream (GEMM1 was last reader of g_Wt) ----
    cudaEventRecord(eF2, 0);
    cudaStreamWaitEvent(s2, eF2, 0);
    k_prepw<<<(256 * HH + 255) / 256, 256, 0, s2>>>(W2, HH, nullptr);
    cudaEventRecord(eJ2, s2);

    // ---- join CSR branch, then gather1 ----
    cudaStreamWaitEvent(0, eJ1, 0);
    k_gather<1><<<(n * 32 + 255) / 256, 256>>>(bias1, nullptr, n);

    // ---- main: BN2 stats + normalize+ReLU -> split bf16 ----
    k_colstats<<<512, HH>>>(p_agg, n, HH, p_sums + 512, p_sums + 768);
    k_bnfinal2<<<1, HH>>>(gamma2, p_sums + 512, p_sums + 768, n);
    k_bnrelu<<<(featElems + 255) / 256, 256>>>(beta2, n);

    // ---- join W2 branch, then GEMM2 + gather2 ----
    cudaStreamWaitEvent(0, eJ2, 0);
    k_mmagemm<<<gemmGrid, 256>>>(p_h2h, p_h2l, p_hlh, n, HH,
                                 nullptr, att_src2, att_dst2);
    k_gather<2><<<(n * 32 + 255) / 256, 256>>>(bias2, out, n);
}